// round 14
// baseline (speedup 1.0000x reference)
#include <cuda_runtime.h>
#include <cuda_fp16.h>
#include <math.h>
#include <stdint.h>

#define NB 32
#define C  512
#define S  3136   // 56*56
#define S4 (S/4)
#define BK 32
#define NCHUNK (S / BK)   // 98

// ---------------- scratch (device globals; no allocations allowed) ----------------
__device__ __half g_eh[(size_t)NB * C * S];   // fp16(4096 * exp(7*(x - rowmax)))
__device__ __half g_xh[(size_t)NB * C * S];   // fp16(x)
__device__ float g_invZ[NB * C];              // 1 / sum(e')
__device__ float g_B[(size_t)NB * C * C];     // raw bilinear logits (pre-softmax)
__device__ float g_wpart[16][NB * C];         // partial column sums of softmax(B)
__device__ float g_opart[8][NB * S];          // partial output sums (d-split)

__device__ __forceinline__ uint32_t smem_u32(const void* p) {
    uint32_t a;
    asm("{ .reg .u64 t; cvta.to.shared.u64 t, %1; cvt.u32.u64 %0, t; }" : "=r"(a) : "l"(p));
    return a;
}

// ---------------- block reductions ----------------
__device__ __forceinline__ float blockReduceMax(float v) {
    __shared__ float sh[32];
    int lane = threadIdx.x & 31, w = threadIdx.x >> 5;
    __syncthreads();
    #pragma unroll
    for (int o = 16; o; o >>= 1) v = fmaxf(v, __shfl_xor_sync(0xffffffffu, v, o));
    if (lane == 0) sh[w] = v;
    __syncthreads();
    int nw = (blockDim.x + 31) >> 5;
    if (w == 0) {
        v = (lane < nw) ? sh[lane] : -INFINITY;
        #pragma unroll
        for (int o = 16; o; o >>= 1) v = fmaxf(v, __shfl_xor_sync(0xffffffffu, v, o));
        if (lane == 0) sh[0] = v;
    }
    __syncthreads();
    return sh[0];
}
__device__ __forceinline__ float blockReduceSum(float v) {
    __shared__ float sh[32];
    int lane = threadIdx.x & 31, w = threadIdx.x >> 5;
    __syncthreads();
    #pragma unroll
    for (int o = 16; o; o >>= 1) v += __shfl_xor_sync(0xffffffffu, v, o);
    if (lane == 0) sh[w] = v;
    __syncthreads();
    int nw = (blockDim.x + 31) >> 5;
    if (w == 0) {
        v = (lane < nw) ? sh[lane] : 0.0f;
        #pragma unroll
        for (int o = 16; o; o >>= 1) v += __shfl_xor_sync(0xffffffffu, v, o);
        if (lane == 0) sh[0] = v;
    }
    __syncthreads();
    return sh[0];
}

// ---------------- kernel 1: rowmax + scaled exp -> fp16; x -> fp16. Single global read via SMEM cache.
__global__ void k_rowexp(const float* __restrict__ x) {
    __shared__ __align__(16) float xs[S];   // 12.5 KB row cache
    size_t row = blockIdx.x;  // n*C + c
    const float4* xr = (const float4*)(x + row * S);
    float4* xs4 = (float4*)xs;
    uint2* er = (uint2*)(g_eh + row * S);   // 4 halves per uint2
    uint2* hr = (uint2*)(g_xh + row * S);

    float m = -INFINITY;
    for (int i = threadIdx.x; i < S4; i += blockDim.x) {
        float4 v = xr[i];
        xs4[i] = v;
        m = fmaxf(m, fmaxf(fmaxf(v.x, v.y), fmaxf(v.z, v.w)));
    }
    m = blockReduceMax(m);

    const float k = 10.098865286222744f;  // 7/ln(2)
    float s = 0.0f;
    for (int i = threadIdx.x; i < S4; i += blockDim.x) {
        float4 v = xs4[i];
        __half2 x01 = __halves2half2(__float2half_rn(v.x), __float2half_rn(v.y));
        __half2 x23 = __halves2half2(__float2half_rn(v.z), __float2half_rn(v.w));
        uint2 ho;
        ho.x = *(uint32_t*)&x01;
        ho.y = *(uint32_t*)&x23;
        hr[i] = ho;
        float e0 = exp2f(fmaf(k, v.x - m, 12.0f));   // 4096 * exp(7*(x-m))
        float e1 = exp2f(fmaf(k, v.y - m, 12.0f));
        float e2 = exp2f(fmaf(k, v.z - m, 12.0f));
        float e3 = exp2f(fmaf(k, v.w - m, 12.0f));
        s += (e0 + e1) + (e2 + e3);
        __half2 h01 = __halves2half2(__float2half_rn(e0), __float2half_rn(e1));
        __half2 h23 = __halves2half2(__float2half_rn(e2), __float2half_rn(e3));
        uint2 o;
        o.x = *(uint32_t*)&h01;
        o.y = *(uint32_t*)&h23;
        er[i] = o;
    }
    s = blockReduceSum(s);
    if (threadIdx.x == 0) g_invZ[row] = 1.0f / s;
}

// ---------------- kernel 2: warp-MMA batched GEMM  B[n] = E[n] @ Xh[n]^T ----------------
// 64x64 CTA tile, 128 threads (4 warps, 2x2), warp tile 32x32, BK=32, 2-stage cp.async.
// 2048 CTAs -> ~6 resident/SM -> work-stealing quantization ~1%.
#define LDA 40
#define TILE_B (64 * LDA * 2)         // 5120 bytes per tile
#define STAGE_B (2 * TILE_B)          // A, B
#define NSTAGE 2
#define SMEM_TOTAL (NSTAGE * STAGE_B) // 20480

__device__ __forceinline__ void cp16(uint32_t saddr, const void* gptr) {
    asm volatile("cp.async.cg.shared.global [%0], [%1], 16;" :: "r"(saddr), "l"(gptr) : "memory");
}

__global__ __launch_bounds__(128) void k_gemm_mma() {
    extern __shared__ __align__(16) unsigned char sm[];

    const int tid = threadIdx.x, lane = tid & 31, wid = tid >> 5;
    const int n = blockIdx.z, tm = blockIdx.y, tn = blockIdx.x;
    const int wm = wid >> 1, wn = wid & 1;   // warp tile: rows wm*32, cols wn*32

    const size_t nb = (size_t)n * C * S;
    const int lr = tid >> 1;             // 0..63
    const int lc = (tid & 1) * 16;       // 0 or 16 (elems)
    const __half* Aptr = g_eh + nb + (size_t)(tm * 64 + lr) * S + lc;
    const __half* Xptr = g_xh + nb + (size_t)(tn * 64 + lr) * S + lc;
    const uint32_t sRow = (uint32_t)(lr * (LDA * 2) + lc * 2);
    const uint32_t smBase = smem_u32(sm);

    const int q = lane >> 3, r8 = lane & 7;
    const uint32_t laneOff = (uint32_t)((((q & 1) << 3) + r8) * (LDA * 2) + ((q >> 1) << 3) * 2);

    float acc[2][4][4];
    #pragma unroll
    for (int mi = 0; mi < 2; mi++)
        #pragma unroll
        for (int ni = 0; ni < 4; ni++)
            #pragma unroll
            for (int j = 0; j < 4; j++) acc[mi][ni][j] = 0.0f;

    auto issue = [&](int it) {
        const int buf = it & 1;
        const int k0 = it * BK;
        const uint32_t sa = smBase + (uint32_t)buf * STAGE_B + sRow;
        const __half* ga = Aptr + k0;
        const __half* gx = Xptr + k0;
        cp16(sa, ga);                   cp16(sa + 16, ga + 8);
        cp16(sa + TILE_B, gx);          cp16(sa + TILE_B + 16, gx + 8);
        asm volatile("cp.async.commit_group;" ::: "memory");
    };

    issue(0);

    for (int it = 0; it < NCHUNK; it++) {
        if (it + 1 < NCHUNK) {
            issue(it + 1);
            asm volatile("cp.async.wait_group 1;" ::: "memory");
        } else {
            asm volatile("cp.async.wait_group 0;" ::: "memory");
        }
        __syncthreads();

        const int buf = it & 1;
        const uint32_t base = smBase + (uint32_t)buf * STAGE_B;
        const uint32_t aB = base + (uint32_t)(wm * 32) * (LDA * 2) + laneOff;
        const uint32_t bB = base + TILE_B + (uint32_t)(wn * 32) * (LDA * 2) + laneOff;

        #pragma unroll
        for (int kk = 0; kk < 2; kk++) {
            uint32_t a[2][4], bh[2][4];
            #pragma unroll
            for (int mi = 0; mi < 2; mi++) {
                asm volatile("ldmatrix.sync.aligned.m8n8.x4.shared.b16 {%0,%1,%2,%3}, [%4];"
                    : "=r"(a[mi][0]), "=r"(a[mi][1]), "=r"(a[mi][2]), "=r"(a[mi][3])
                    : "r"(aB + (uint32_t)(mi * 16) * (LDA * 2) + (uint32_t)kk * 32));
            }
            #pragma unroll
            for (int p = 0; p < 2; p++) {
                asm volatile("ldmatrix.sync.aligned.m8n8.x4.shared.b16 {%0,%1,%2,%3}, [%4];"
                    : "=r"(bh[p][0]), "=r"(bh[p][1]), "=r"(bh[p][2]), "=r"(bh[p][3])
                    : "r"(bB + (uint32_t)(p * 16) * (LDA * 2) + (uint32_t)kk * 32));
            }
            #pragma unroll
            for (int mi = 0; mi < 2; mi++) {
                #pragma unroll
                for (int p = 0; p < 2; p++) {
                    asm volatile(
                        "mma.sync.aligned.m16n8k16.row.col.f32.f16.f16.f32 "
                        "{%0,%1,%2,%3},{%4,%5,%6,%7},{%8,%9},{%0,%1,%2,%3};"
                        : "+f"(acc[mi][2*p][0]), "+f"(acc[mi][2*p][1]),
                          "+f"(acc[mi][2*p][2]), "+f"(acc[mi][2*p][3])
                        : "r"(a[mi][0]), "r"(a[mi][1]), "r"(a[mi][2]), "r"(a[mi][3]),
                          "r"(bh[p][0]), "r"(bh[p][2]));
                    asm volatile(
                        "mma.sync.aligned.m16n8k16.row.col.f32.f16.f16.f32 "
                        "{%0,%1,%2,%3},{%4,%5,%6,%7},{%8,%9},{%0,%1,%2,%3};"
                        : "+f"(acc[mi][2*p+1][0]), "+f"(acc[mi][2*p+1][1]),
                          "+f"(acc[mi][2*p+1][2]), "+f"(acc[mi][2*p+1][3])
                        : "r"(a[mi][0]), "r"(a[mi][1]), "r"(a[mi][2]), "r"(a[mi][3]),
                          "r"(bh[p][1]), "r"(bh[p][3]));
                }
            }
        }
        __syncthreads();   // protect buf before it+2 overwrites it
    }

    // epilogue: acc -> g_B
    float* Cn = g_B + (size_t)n * C * C;
    const int mrow0 = tm * 64 + wm * 32 + (lane >> 2);
    const int ncol0 = tn * 64 + wn * 32 + (lane & 3) * 2;
    #pragma unroll
    for (int mi = 0; mi < 2; mi++) {
        #pragma unroll
        for (int ni = 0; ni < 4; ni++) {
            const int r = mrow0 + mi * 16;
            const int cc = ncol0 + ni * 8;
            *(float2*)&Cn[(size_t)r * C + cc]       = make_float2(acc[mi][ni][0], acc[mi][ni][1]);
            *(float2*)&Cn[(size_t)(r + 8) * C + cc] = make_float2(acc[mi][ni][2], acc[mi][ni][3]);
        }
    }
}

// ---------------- kernel 3: fused row-softmax + partial column-sum ----------------
// grid (NB, 16): CTA = 32 rows of batch n. Warp per row (4 rows/warp).
__global__ void k_bsm() {
    __shared__ float cac[8][C];   // 16 KB
    const int n = blockIdx.x, cb = blockIdx.y;
    const int lane = threadIdx.x & 31, wid = threadIdx.x >> 5;

    float wacc[4][4];
    #pragma unroll
    for (int q = 0; q < 4; q++)
        #pragma unroll
        for (int j = 0; j < 4; j++) wacc[q][j] = 0.0f;

    for (int r = wid; r < 32; r += 8) {
        const int row = cb * 32 + r;
        const float* Br = g_B + (size_t)n * C * C + (size_t)row * C;
        const float iz = g_invZ[n * C + row];
        float4 v[4];
        float m = -INFINITY;
        #pragma unroll
        for (int q = 0; q < 4; q++) {
            v[q] = *(const float4*)(Br + q * 128 + lane * 4);
            v[q].x *= iz; v[q].y *= iz; v[q].z *= iz; v[q].w *= iz;
            m = fmaxf(m, fmaxf(fmaxf(v[q].x, v[q].y), fmaxf(v[q].z, v[q].w)));
        }
        #pragma unroll
        for (int o = 16; o; o >>= 1) m = fmaxf(m, __shfl_xor_sync(0xffffffffu, m, o));
        float s = 0.0f;
        #pragma unroll
        for (int q = 0; q < 4; q++) {
            v[q].x = __expf(v[q].x - m); v[q].y = __expf(v[q].y - m);
            v[q].z = __expf(v[q].z - m); v[q].w = __expf(v[q].w - m);
            s += (v[q].x + v[q].y) + (v[q].z + v[q].w);
        }
        #pragma unroll
        for (int o = 16; o; o >>= 1) s += __shfl_xor_sync(0xffffffffu, s, o);
        const float inv = 1.0f / s;
        #pragma unroll
        for (int q = 0; q < 4; q++) {
            wacc[q][0] = fmaf(v[q].x, inv, wacc[q][0]);
            wacc[q][1] = fmaf(v[q].y, inv, wacc[q][1]);
            wacc[q][2] = fmaf(v[q].z, inv, wacc[q][2]);
            wacc[q][3] = fmaf(v[q].w, inv, wacc[q][3]);
        }
    }
    #pragma unroll
    for (int q = 0; q < 4; q++)
        *(float4*)&cac[wid][q * 128 + lane * 4] =
            make_float4(wacc[q][0], wacc[q][1], wacc[q][2], wacc[q][3]);
    __syncthreads();
    #pragma unroll
    for (int h = 0; h < 2; h++) {
        const int col = threadIdx.x + h * 256;
        float s = 0.0f;
        #pragma unroll
        for (int w = 0; w < 8; w++) s += cac[w][col];
        g_wpart[cb][n * C + col] = s;
    }
}

// ---------------- kernel 4: d-split partial output sums ----------------
#define S2 (S / 2)   // 1568 half2 per row
__global__ void k_out() {
    const int n = blockIdx.y;
    const int dq = blockIdx.z;                 // 0..7
    const int s2 = blockIdx.x * 256 + threadIdx.x;
    __shared__ float ws[64];
    if (threadIdx.x < 64) {
        const int d = dq * 64 + threadIdx.x;
        float s = 0.0f;
        #pragma unroll
        for (int w = 0; w < 16; w++) s += g_wpart[w][n * C + d];
        ws[threadIdx.x] = s;
    }
    __syncthreads();
    if (s2 >= S2) return;
    const __half2* fb = (const __half2*)(g_xh + (size_t)n * C * S + (size_t)(dq * 64) * S) + s2;
    float a0 = 0, a1 = 0, b0 = 0, b1 = 0;
    #pragma unroll 4
    for (int d = 0; d < 64; d += 2) {
        float2 f0 = __half22float2(fb[(size_t)d * S2]);
        float2 f1 = __half22float2(fb[(size_t)(d + 1) * S2]);
        a0 = fmaf(ws[d], f0.x, a0);
        a1 = fmaf(ws[d], f0.y, a1);
        b0 = fmaf(ws[d + 1], f1.x, b0);
        b1 = fmaf(ws[d + 1], f1.y, b1);
    }
    float2* o = (float2*)(g_opart[dq] + (size_t)n * S) + s2;
    *o = make_float2(a0 + b0, a1 + b1);
}

// ---------------- kernel 5: combine partials into out ----------------
__global__ void k_comb(float* __restrict__ out) {
    const int i4 = blockIdx.x * 256 + threadIdx.x;   // float4 index, NB*S/4 = 25088
    if (i4 >= NB * S / 4) return;
    float4 acc = make_float4(0.f, 0.f, 0.f, 0.f);
    #pragma unroll
    for (int q = 0; q < 8; q++) {
        float4 v = ((const float4*)g_opart[q])[i4];
        acc.x += v.x; acc.y += v.y; acc.z += v.z; acc.w += v.w;
    }
    ((float4*)out)[i4] = acc;
}

extern "C" void kernel_launch(void* const* d_in, const int* in_sizes, int n_in,
                              void* d_out, int out_size) {
    const float* x = (const float*)d_in[0];
    float* out = (float*)d_out;

    cudaFuncSetAttribute(k_gemm_mma, cudaFuncAttributeMaxDynamicSharedMemorySize, SMEM_TOTAL);

    k_rowexp<<<NB * C, 256>>>(x);

    dim3 g2(C / 64, C / 64, NB);     // (8,8,32) = 2048 CTAs
    k_gemm_mma<<<g2, 128, SMEM_TOTAL>>>();

    dim3 g3(NB, 16);                 // (32,16) = 512 CTAs
    k_bsm<<<g3, 256>>>();

    dim3 g4((S2 + 255) / 256, NB, 8);  // (7,32,8) = 1792 CTAs
    k_out<<<g4, 256>>>();

    k_comb<<<(NB * S / 4 + 255) / 256, 256>>>(out);
}

// round 15
// speedup vs baseline: 1.1718x; 1.1718x over previous
#include <cuda_runtime.h>
#include <cuda_fp16.h>
#include <math.h>
#include <stdint.h>

#define NB 32
#define C  512
#define S  3136   // 56*56
#define S4 (S/4)
#define BK 32
#define NCHUNK_H (S / BK / 2)   // 49 chunks per K-half

// ---------------- scratch (device globals; no allocations allowed) ----------------
__device__ __half g_eh[(size_t)NB * C * S];   // fp16(4096 * exp(7*(x - rowmax)))
__device__ __half g_xh[(size_t)NB * C * S];   // fp16(x)
__device__ float g_invZ[NB * C];              // 1 / sum(e')
__device__ float g_Bp[2][(size_t)NB * C * C]; // split-K partial bilinear logits
__device__ float g_wpart[16][NB * C];         // partial column sums of softmax(B)
__device__ float g_opart[8][NB * S];          // partial output sums (d-split)

__device__ __forceinline__ uint32_t smem_u32(const void* p) {
    uint32_t a;
    asm("{ .reg .u64 t; cvta.to.shared.u64 t, %1; cvt.u32.u64 %0, t; }" : "=r"(a) : "l"(p));
    return a;
}

// ---------------- block reductions ----------------
__device__ __forceinline__ float blockReduceMax(float v) {
    __shared__ float sh[32];
    int lane = threadIdx.x & 31, w = threadIdx.x >> 5;
    __syncthreads();
    #pragma unroll
    for (int o = 16; o; o >>= 1) v = fmaxf(v, __shfl_xor_sync(0xffffffffu, v, o));
    if (lane == 0) sh[w] = v;
    __syncthreads();
    int nw = (blockDim.x + 31) >> 5;
    if (w == 0) {
        v = (lane < nw) ? sh[lane] : -INFINITY;
        #pragma unroll
        for (int o = 16; o; o >>= 1) v = fmaxf(v, __shfl_xor_sync(0xffffffffu, v, o));
        if (lane == 0) sh[0] = v;
    }
    __syncthreads();
    return sh[0];
}
__device__ __forceinline__ float blockReduceSum(float v) {
    __shared__ float sh[32];
    int lane = threadIdx.x & 31, w = threadIdx.x >> 5;
    __syncthreads();
    #pragma unroll
    for (int o = 16; o; o >>= 1) v += __shfl_xor_sync(0xffffffffu, v, o);
    if (lane == 0) sh[w] = v;
    __syncthreads();
    int nw = (blockDim.x + 31) >> 5;
    if (w == 0) {
        v = (lane < nw) ? sh[lane] : 0.0f;
        #pragma unroll
        for (int o = 16; o; o >>= 1) v += __shfl_xor_sync(0xffffffffu, v, o);
        if (lane == 0) sh[0] = v;
    }
    __syncthreads();
    return sh[0];
}

// ---------------- kernel 1: rowmax + scaled exp -> fp16; x -> fp16. Single global read via SMEM cache.
__global__ void k_rowexp(const float* __restrict__ x) {
    __shared__ __align__(16) float xs[S];   // 12.5 KB row cache
    size_t row = blockIdx.x;  // n*C + c
    const float4* xr = (const float4*)(x + row * S);
    float4* xs4 = (float4*)xs;
    uint2* er = (uint2*)(g_eh + row * S);   // 4 halves per uint2
    uint2* hr = (uint2*)(g_xh + row * S);

    float m = -INFINITY;
    for (int i = threadIdx.x; i < S4; i += blockDim.x) {
        float4 v = xr[i];
        xs4[i] = v;
        m = fmaxf(m, fmaxf(fmaxf(v.x, v.y), fmaxf(v.z, v.w)));
    }
    m = blockReduceMax(m);

    const float k = 10.098865286222744f;  // 7/ln(2)
    float s = 0.0f;
    for (int i = threadIdx.x; i < S4; i += blockDim.x) {
        float4 v = xs4[i];
        __half2 x01 = __halves2half2(__float2half_rn(v.x), __float2half_rn(v.y));
        __half2 x23 = __halves2half2(__float2half_rn(v.z), __float2half_rn(v.w));
        uint2 ho;
        ho.x = *(uint32_t*)&x01;
        ho.y = *(uint32_t*)&x23;
        hr[i] = ho;
        float e0 = exp2f(fmaf(k, v.x - m, 12.0f));   // 4096 * exp(7*(x-m))
        float e1 = exp2f(fmaf(k, v.y - m, 12.0f));
        float e2 = exp2f(fmaf(k, v.z - m, 12.0f));
        float e3 = exp2f(fmaf(k, v.w - m, 12.0f));
        s += (e0 + e1) + (e2 + e3);
        __half2 h01 = __halves2half2(__float2half_rn(e0), __float2half_rn(e1));
        __half2 h23 = __halves2half2(__float2half_rn(e2), __float2half_rn(e3));
        uint2 o;
        o.x = *(uint32_t*)&h01;
        o.y = *(uint32_t*)&h23;
        er[i] = o;
    }
    s = blockReduceSum(s);
    if (threadIdx.x == 0) g_invZ[row] = 1.0f / s;
}

// ---------------- kernel 2: split-K warp-MMA batched GEMM  Bp[kh][n] = E[n][:,Kh] @ Xh[n][:,Kh]^T
// 128x128 CTA tile, BK=32, 8 warps (4x2), each warp 32x64; K split in 2 halves.
// grid (4, 8, 32): y = tm | (kh<<2). 1024 CTA-works -> makespan quantization ~1%.
#define LDA 40
#define TILE_B (128 * LDA * 2)        // 10240 bytes per tile
#define STAGE_B (2 * TILE_B)          // A, B
#define NSTAGE 2
#define SMEM_TOTAL (NSTAGE * STAGE_B) // 40960

__device__ __forceinline__ void cp16(uint32_t saddr, const void* gptr) {
    asm volatile("cp.async.cg.shared.global [%0], [%1], 16;" :: "r"(saddr), "l"(gptr) : "memory");
}

__global__ __launch_bounds__(256) void k_gemm_mma() {
    extern __shared__ __align__(16) unsigned char sm[];

    const int tid = threadIdx.x, lane = tid & 31, wid = tid >> 5;
    const int n = blockIdx.z, tn = blockIdx.x;
    const int tm = blockIdx.y & 3, kh = blockIdx.y >> 2;
    const int wm = wid >> 1, wn = wid & 1;   // warp tile: rows wm*32, cols wn*64

    const size_t nb = (size_t)n * C * S;
    const int lr = tid >> 1;             // 0..127
    const int lc = (tid & 1) * 16;       // 0 or 16 (elems)
    const size_t kOff = (size_t)kh * (S / 2);
    const __half* Aptr = g_eh + nb + (size_t)(tm * 128 + lr) * S + kOff + lc;
    const __half* Xptr = g_xh + nb + (size_t)(tn * 128 + lr) * S + kOff + lc;
    const uint32_t sRow = (uint32_t)(lr * (LDA * 2) + lc * 2);
    const uint32_t smBase = smem_u32(sm);

    const int q = lane >> 3, r8 = lane & 7;
    const uint32_t laneOff = (uint32_t)((((q & 1) << 3) + r8) * (LDA * 2) + ((q >> 1) << 3) * 2);

    float acc[2][8][4];
    #pragma unroll
    for (int mi = 0; mi < 2; mi++)
        #pragma unroll
        for (int ni = 0; ni < 8; ni++)
            #pragma unroll
            for (int j = 0; j < 4; j++) acc[mi][ni][j] = 0.0f;

    auto issue = [&](int it) {
        const int buf = it & 1;
        const int k0 = it * BK;
        const uint32_t sa = smBase + (uint32_t)buf * STAGE_B + sRow;
        const __half* ga = Aptr + k0;
        const __half* gx = Xptr + k0;
        cp16(sa, ga);                   cp16(sa + 16, ga + 8);
        cp16(sa + TILE_B, gx);          cp16(sa + TILE_B + 16, gx + 8);
        asm volatile("cp.async.commit_group;" ::: "memory");
    };

    issue(0);

    for (int it = 0; it < NCHUNK_H; it++) {
        if (it + 1 < NCHUNK_H) {
            issue(it + 1);
            asm volatile("cp.async.wait_group 1;" ::: "memory");
        } else {
            asm volatile("cp.async.wait_group 0;" ::: "memory");
        }
        __syncthreads();

        const int buf = it & 1;
        const uint32_t base = smBase + (uint32_t)buf * STAGE_B;
        const uint32_t aB = base + (uint32_t)(wm * 32) * (LDA * 2) + laneOff;
        const uint32_t bB = base + TILE_B + (uint32_t)(wn * 64) * (LDA * 2) + laneOff;

        #pragma unroll
        for (int kk = 0; kk < 2; kk++) {
            uint32_t a[2][4], bh[4][4];
            #pragma unroll
            for (int mi = 0; mi < 2; mi++) {
                asm volatile("ldmatrix.sync.aligned.m8n8.x4.shared.b16 {%0,%1,%2,%3}, [%4];"
                    : "=r"(a[mi][0]), "=r"(a[mi][1]), "=r"(a[mi][2]), "=r"(a[mi][3])
                    : "r"(aB + (uint32_t)(mi * 16) * (LDA * 2) + (uint32_t)kk * 32));
            }
            #pragma unroll
            for (int p = 0; p < 4; p++) {
                asm volatile("ldmatrix.sync.aligned.m8n8.x4.shared.b16 {%0,%1,%2,%3}, [%4];"
                    : "=r"(bh[p][0]), "=r"(bh[p][1]), "=r"(bh[p][2]), "=r"(bh[p][3])
                    : "r"(bB + (uint32_t)(p * 16) * (LDA * 2) + (uint32_t)kk * 32));
            }
            #pragma unroll
            for (int mi = 0; mi < 2; mi++) {
                #pragma unroll
                for (int p = 0; p < 4; p++) {
                    asm volatile(
                        "mma.sync.aligned.m16n8k16.row.col.f32.f16.f16.f32 "
                        "{%0,%1,%2,%3},{%4,%5,%6,%7},{%8,%9},{%0,%1,%2,%3};"
                        : "+f"(acc[mi][2*p][0]), "+f"(acc[mi][2*p][1]),
                          "+f"(acc[mi][2*p][2]), "+f"(acc[mi][2*p][3])
                        : "r"(a[mi][0]), "r"(a[mi][1]), "r"(a[mi][2]), "r"(a[mi][3]),
                          "r"(bh[p][0]), "r"(bh[p][2]));
                    asm volatile(
                        "mma.sync.aligned.m16n8k16.row.col.f32.f16.f16.f32 "
                        "{%0,%1,%2,%3},{%4,%5,%6,%7},{%8,%9},{%0,%1,%2,%3};"
                        : "+f"(acc[mi][2*p+1][0]), "+f"(acc[mi][2*p+1][1]),
                          "+f"(acc[mi][2*p+1][2]), "+f"(acc[mi][2*p+1][3])
                        : "r"(a[mi][0]), "r"(a[mi][1]), "r"(a[mi][2]), "r"(a[mi][3]),
                          "r"(bh[p][1]), "r"(bh[p][3]));
                }
            }
        }
        __syncthreads();   // protect buf before it+2 overwrites it
    }

    // epilogue: acc -> g_Bp[kh]
    float* Cn = g_Bp[kh] + (size_t)n * C * C;
    const int mrow0 = tm * 128 + wm * 32 + (lane >> 2);
    const int ncol0 = tn * 128 + wn * 64 + (lane & 3) * 2;
    #pragma unroll
    for (int mi = 0; mi < 2; mi++) {
        #pragma unroll
        for (int ni = 0; ni < 8; ni++) {
            const int r = mrow0 + mi * 16;
            const int cc = ncol0 + ni * 8;
            *(float2*)&Cn[(size_t)r * C + cc]       = make_float2(acc[mi][ni][0], acc[mi][ni][1]);
            *(float2*)&Cn[(size_t)(r + 8) * C + cc] = make_float2(acc[mi][ni][2], acc[mi][ni][3]);
        }
    }
}

// ---------------- kernel 3: fused split-K combine + row-softmax + partial column-sum ----------------
// grid (NB, 16): CTA = 32 rows of batch n. Warp per row (4 rows/warp).
__global__ void k_bsm() {
    __shared__ float cac[8][C];   // 16 KB
    const int n = blockIdx.x, cb = blockIdx.y;
    const int lane = threadIdx.x & 31, wid = threadIdx.x >> 5;

    float wacc[4][4];
    #pragma unroll
    for (int q = 0; q < 4; q++)
        #pragma unroll
        for (int j = 0; j < 4; j++) wacc[q][j] = 0.0f;

    for (int r = wid; r < 32; r += 8) {
        const int row = cb * 32 + r;
        const size_t ro = (size_t)n * C * C + (size_t)row * C;
        const float* B0 = g_Bp[0] + ro;
        const float* B1 = g_Bp[1] + ro;
        const float iz = g_invZ[n * C + row];
        float4 v[4];
        float m = -INFINITY;
        #pragma unroll
        for (int q = 0; q < 4; q++) {
            float4 u0 = *(const float4*)(B0 + q * 128 + lane * 4);
            float4 u1 = *(const float4*)(B1 + q * 128 + lane * 4);
            v[q].x = (u0.x + u1.x) * iz;
            v[q].y = (u0.y + u1.y) * iz;
            v[q].z = (u0.z + u1.z) * iz;
            v[q].w = (u0.w + u1.w) * iz;
            m = fmaxf(m, fmaxf(fmaxf(v[q].x, v[q].y), fmaxf(v[q].z, v[q].w)));
        }
        #pragma unroll
        for (int o = 16; o; o >>= 1) m = fmaxf(m, __shfl_xor_sync(0xffffffffu, m, o));
        float s = 0.0f;
        #pragma unroll
        for (int q = 0; q < 4; q++) {
            v[q].x = __expf(v[q].x - m); v[q].y = __expf(v[q].y - m);
            v[q].z = __expf(v[q].z - m); v[q].w = __expf(v[q].w - m);
            s += (v[q].x + v[q].y) + (v[q].z + v[q].w);
        }
        #pragma unroll
        for (int o = 16; o; o >>= 1) s += __shfl_xor_sync(0xffffffffu, s, o);
        const float inv = 1.0f / s;
        #pragma unroll
        for (int q = 0; q < 4; q++) {
            wacc[q][0] = fmaf(v[q].x, inv, wacc[q][0]);
            wacc[q][1] = fmaf(v[q].y, inv, wacc[q][1]);
            wacc[q][2] = fmaf(v[q].z, inv, wacc[q][2]);
            wacc[q][3] = fmaf(v[q].w, inv, wacc[q][3]);
        }
    }
    #pragma unroll
    for (int q = 0; q < 4; q++)
        *(float4*)&cac[wid][q * 128 + lane * 4] =
            make_float4(wacc[q][0], wacc[q][1], wacc[q][2], wacc[q][3]);
    __syncthreads();
    #pragma unroll
    for (int h = 0; h < 2; h++) {
        const int col = threadIdx.x + h * 256;
        float s = 0.0f;
        #pragma unroll
        for (int w = 0; w < 8; w++) s += cac[w][col];
        g_wpart[cb][n * C + col] = s;
    }
}

// ---------------- kernel 4: d-split partial output sums ----------------
#define S2 (S / 2)   // 1568 half2 per row
__global__ void k_out() {
    const int n = blockIdx.y;
    const int dq = blockIdx.z;                 // 0..7
    const int s2 = blockIdx.x * 256 + threadIdx.x;
    __shared__ float ws[64];
    if (threadIdx.x < 64) {
        const int d = dq * 64 + threadIdx.x;
        float s = 0.0f;
        #pragma unroll
        for (int w = 0; w < 16; w++) s += g_wpart[w][n * C + d];
        ws[threadIdx.x] = s;
    }
    __syncthreads();
    if (s2 >= S2) return;
    const __half2* fb = (const __half2*)(g_xh + (size_t)n * C * S + (size_t)(dq * 64) * S) + s2;
    float a0 = 0, a1 = 0, b0 = 0, b1 = 0;
    #pragma unroll 4
    for (int d = 0; d < 64; d += 2) {
        float2 f0 = __half22float2(fb[(size_t)d * S2]);
        float2 f1 = __half22float2(fb[(size_t)(d + 1) * S2]);
        a0 = fmaf(ws[d], f0.x, a0);
        a1 = fmaf(ws[d], f0.y, a1);
        b0 = fmaf(ws[d + 1], f1.x, b0);
        b1 = fmaf(ws[d + 1], f1.y, b1);
    }
    float2* o = (float2*)(g_opart[dq] + (size_t)n * S) + s2;
    *o = make_float2(a0 + b0, a1 + b1);
}

// ---------------- kernel 5: combine partials into out ----------------
__global__ void k_comb(float* __restrict__ out) {
    const int i4 = blockIdx.x * 256 + threadIdx.x;   // float4 index, NB*S/4 = 25088
    if (i4 >= NB * S / 4) return;
    float4 acc = make_float4(0.f, 0.f, 0.f, 0.f);
    #pragma unroll
    for (int q = 0; q < 8; q++) {
        float4 v = ((const float4*)g_opart[q])[i4];
        acc.x += v.x; acc.y += v.y; acc.z += v.z; acc.w += v.w;
    }
    ((float4*)out)[i4] = acc;
}

extern "C" void kernel_launch(void* const* d_in, const int* in_sizes, int n_in,
                              void* d_out, int out_size) {
    const float* x = (const float*)d_in[0];
    float* out = (float*)d_out;

    cudaFuncSetAttribute(k_gemm_mma, cudaFuncAttributeMaxDynamicSharedMemorySize, SMEM_TOTAL);

    k_rowexp<<<NB * C, 256>>>(x);

    dim3 g2(C / 128, 8, NB);         // (4, 4 tm x 2 kh, 32) = 1024 CTA-works
    k_gemm_mma<<<g2, 256, SMEM_TOTAL>>>();

    dim3 g3(NB, 16);                 // (32,16) = 512 CTAs
    k_bsm<<<g3, 256>>>();

    dim3 g4((S2 + 255) / 256, NB, 8);  // (7,32,8) = 1792 CTAs
    k_out<<<g4, 256>>>();

    k_comb<<<(NB * S / 4 + 255) / 256, 256>>>(out);
}

// round 16
// speedup vs baseline: 1.2208x; 1.0418x over previous
#include <cuda_runtime.h>
#include <cuda_fp16.h>
#include <math.h>
#include <stdint.h>

#define NB 32
#define C  512
#define S  3136   // 56*56
#define S4 (S/4)
#define BK 32
#define NCHUNK_H (S / BK / 2)   // 49 chunks per K-half
#define GRP 8                   // batches per pipeline group
#define NGRP (NB / GRP)         // 4

// ---------------- scratch (device globals; no allocations allowed) ----------------
__device__ __half g_eh[(size_t)NB * C * S];   // fp16(4096 * exp(7*(x - rowmax)))
__device__ __half g_xh[(size_t)NB * C * S];   // fp16(x)
__device__ float g_invZ[NB * C];              // 1 / sum(e')
__device__ float g_Bp[2][(size_t)NB * C * C]; // split-K partial bilinear logits
__device__ float g_wpart[16][NB * C];         // partial column sums of softmax(B)
__device__ float g_opart[8][NB * S];          // partial output sums (d-split)

__device__ __forceinline__ uint32_t smem_u32(const void* p) {
    uint32_t a;
    asm("{ .reg .u64 t; cvta.to.shared.u64 t, %1; cvt.u32.u64 %0, t; }" : "=r"(a) : "l"(p));
    return a;
}

// ---------------- block reductions ----------------
__device__ __forceinline__ float blockReduceMax(float v) {
    __shared__ float sh[32];
    int lane = threadIdx.x & 31, w = threadIdx.x >> 5;
    __syncthreads();
    #pragma unroll
    for (int o = 16; o; o >>= 1) v = fmaxf(v, __shfl_xor_sync(0xffffffffu, v, o));
    if (lane == 0) sh[w] = v;
    __syncthreads();
    int nw = (blockDim.x + 31) >> 5;
    if (w == 0) {
        v = (lane < nw) ? sh[lane] : -INFINITY;
        #pragma unroll
        for (int o = 16; o; o >>= 1) v = fmaxf(v, __shfl_xor_sync(0xffffffffu, v, o));
        if (lane == 0) sh[0] = v;
    }
    __syncthreads();
    return sh[0];
}
__device__ __forceinline__ float blockReduceSum(float v) {
    __shared__ float sh[32];
    int lane = threadIdx.x & 31, w = threadIdx.x >> 5;
    __syncthreads();
    #pragma unroll
    for (int o = 16; o; o >>= 1) v += __shfl_xor_sync(0xffffffffu, v, o);
    if (lane == 0) sh[w] = v;
    __syncthreads();
    int nw = (blockDim.x + 31) >> 5;
    if (w == 0) {
        v = (lane < nw) ? sh[lane] : 0.0f;
        #pragma unroll
        for (int o = 16; o; o >>= 1) v += __shfl_xor_sync(0xffffffffu, v, o);
        if (lane == 0) sh[0] = v;
    }
    __syncthreads();
    return sh[0];
}

// ---------------- kernel 1: rowmax + scaled exp -> fp16; x -> fp16 ----------------
__global__ void k_rowexp(const float* __restrict__ x, int row0) {
    __shared__ __align__(16) float xs[S];   // 12.5 KB row cache
    size_t row = (size_t)row0 + blockIdx.x;  // n*C + c
    const float4* xr = (const float4*)(x + row * S);
    float4* xs4 = (float4*)xs;
    uint2* er = (uint2*)(g_eh + row * S);   // 4 halves per uint2
    uint2* hr = (uint2*)(g_xh + row * S);

    float m = -INFINITY;
    for (int i = threadIdx.x; i < S4; i += blockDim.x) {
        float4 v = xr[i];
        xs4[i] = v;
        m = fmaxf(m, fmaxf(fmaxf(v.x, v.y), fmaxf(v.z, v.w)));
    }
    m = blockReduceMax(m);

    const float k = 10.098865286222744f;  // 7/ln(2)
    float s = 0.0f;
    for (int i = threadIdx.x; i < S4; i += blockDim.x) {
        float4 v = xs4[i];
        __half2 x01 = __halves2half2(__float2half_rn(v.x), __float2half_rn(v.y));
        __half2 x23 = __halves2half2(__float2half_rn(v.z), __float2half_rn(v.w));
        uint2 ho;
        ho.x = *(uint32_t*)&x01;
        ho.y = *(uint32_t*)&x23;
        hr[i] = ho;
        float e0 = exp2f(fmaf(k, v.x - m, 12.0f));   // 4096 * exp(7*(x-m))
        float e1 = exp2f(fmaf(k, v.y - m, 12.0f));
        float e2 = exp2f(fmaf(k, v.z - m, 12.0f));
        float e3 = exp2f(fmaf(k, v.w - m, 12.0f));
        s += (e0 + e1) + (e2 + e3);
        __half2 h01 = __halves2half2(__float2half_rn(e0), __float2half_rn(e1));
        __half2 h23 = __halves2half2(__float2half_rn(e2), __float2half_rn(e3));
        uint2 o;
        o.x = *(uint32_t*)&h01;
        o.y = *(uint32_t*)&h23;
        er[i] = o;
    }
    s = blockReduceSum(s);
    if (threadIdx.x == 0) g_invZ[row] = 1.0f / s;
}

// ---------------- kernel 2: split-K warp-MMA batched GEMM ----------------
#define LDA 40
#define TILE_B (128 * LDA * 2)        // 10240 bytes per tile
#define STAGE_B (2 * TILE_B)          // A, B
#define NSTAGE 2
#define SMEM_TOTAL (NSTAGE * STAGE_B) // 40960

__device__ __forceinline__ void cp16(uint32_t saddr, const void* gptr) {
    asm volatile("cp.async.cg.shared.global [%0], [%1], 16;" :: "r"(saddr), "l"(gptr) : "memory");
}

__global__ __launch_bounds__(256) void k_gemm_mma(int n0) {
    extern __shared__ __align__(16) unsigned char sm[];

    const int tid = threadIdx.x, lane = tid & 31, wid = tid >> 5;
    const int n = n0 + blockIdx.z, tn = blockIdx.x;
    const int tm = blockIdx.y & 3, kh = blockIdx.y >> 2;
    const int wm = wid >> 1, wn = wid & 1;   // warp tile: rows wm*32, cols wn*64

    const size_t nb = (size_t)n * C * S;
    const int lr = tid >> 1;             // 0..127
    const int lc = (tid & 1) * 16;       // 0 or 16 (elems)
    const size_t kOff = (size_t)kh * (S / 2);
    const __half* Aptr = g_eh + nb + (size_t)(tm * 128 + lr) * S + kOff + lc;
    const __half* Xptr = g_xh + nb + (size_t)(tn * 128 + lr) * S + kOff + lc;
    const uint32_t sRow = (uint32_t)(lr * (LDA * 2) + lc * 2);
    const uint32_t smBase = smem_u32(sm);

    const int q = lane >> 3, r8 = lane & 7;
    const uint32_t laneOff = (uint32_t)((((q & 1) << 3) + r8) * (LDA * 2) + ((q >> 1) << 3) * 2);

    float acc[2][8][4];
    #pragma unroll
    for (int mi = 0; mi < 2; mi++)
        #pragma unroll
        for (int ni = 0; ni < 8; ni++)
            #pragma unroll
            for (int j = 0; j < 4; j++) acc[mi][ni][j] = 0.0f;

    auto issue = [&](int it) {
        const int buf = it & 1;
        const int k0 = it * BK;
        const uint32_t sa = smBase + (uint32_t)buf * STAGE_B + sRow;
        const __half* ga = Aptr + k0;
        const __half* gx = Xptr + k0;
        cp16(sa, ga);                   cp16(sa + 16, ga + 8);
        cp16(sa + TILE_B, gx);          cp16(sa + TILE_B + 16, gx + 8);
        asm volatile("cp.async.commit_group;" ::: "memory");
    };

    issue(0);

    for (int it = 0; it < NCHUNK_H; it++) {
        if (it + 1 < NCHUNK_H) {
            issue(it + 1);
            asm volatile("cp.async.wait_group 1;" ::: "memory");
        } else {
            asm volatile("cp.async.wait_group 0;" ::: "memory");
        }
        __syncthreads();

        const int buf = it & 1;
        const uint32_t base = smBase + (uint32_t)buf * STAGE_B;
        const uint32_t aB = base + (uint32_t)(wm * 32) * (LDA * 2) + laneOff;
        const uint32_t bB = base + TILE_B + (uint32_t)(wn * 64) * (LDA * 2) + laneOff;

        #pragma unroll
        for (int kk = 0; kk < 2; kk++) {
            uint32_t a[2][4], bh[4][4];
            #pragma unroll
            for (int mi = 0; mi < 2; mi++) {
                asm volatile("ldmatrix.sync.aligned.m8n8.x4.shared.b16 {%0,%1,%2,%3}, [%4];"
                    : "=r"(a[mi][0]), "=r"(a[mi][1]), "=r"(a[mi][2]), "=r"(a[mi][3])
                    : "r"(aB + (uint32_t)(mi * 16) * (LDA * 2) + (uint32_t)kk * 32));
            }
            #pragma unroll
            for (int p = 0; p < 4; p++) {
                asm volatile("ldmatrix.sync.aligned.m8n8.x4.shared.b16 {%0,%1,%2,%3}, [%4];"
                    : "=r"(bh[p][0]), "=r"(bh[p][1]), "=r"(bh[p][2]), "=r"(bh[p][3])
                    : "r"(bB + (uint32_t)(p * 16) * (LDA * 2) + (uint32_t)kk * 32));
            }
            #pragma unroll
            for (int mi = 0; mi < 2; mi++) {
                #pragma unroll
                for (int p = 0; p < 4; p++) {
                    asm volatile(
                        "mma.sync.aligned.m16n8k16.row.col.f32.f16.f16.f32 "
                        "{%0,%1,%2,%3},{%4,%5,%6,%7},{%8,%9},{%0,%1,%2,%3};"
                        : "+f"(acc[mi][2*p][0]), "+f"(acc[mi][2*p][1]),
                          "+f"(acc[mi][2*p][2]), "+f"(acc[mi][2*p][3])
                        : "r"(a[mi][0]), "r"(a[mi][1]), "r"(a[mi][2]), "r"(a[mi][3]),
                          "r"(bh[p][0]), "r"(bh[p][2]));
                    asm volatile(
                        "mma.sync.aligned.m16n8k16.row.col.f32.f16.f16.f32 "
                        "{%0,%1,%2,%3},{%4,%5,%6,%7},{%8,%9},{%0,%1,%2,%3};"
                        : "+f"(acc[mi][2*p+1][0]), "+f"(acc[mi][2*p+1][1]),
                          "+f"(acc[mi][2*p+1][2]), "+f"(acc[mi][2*p+1][3])
                        : "r"(a[mi][0]), "r"(a[mi][1]), "r"(a[mi][2]), "r"(a[mi][3]),
                          "r"(bh[p][1]), "r"(bh[p][3]));
                }
            }
        }
        __syncthreads();   // protect buf before it+2 overwrites it
    }

    // epilogue: acc -> g_Bp[kh]
    float* Cn = g_Bp[kh] + (size_t)n * C * C;
    const int mrow0 = tm * 128 + wm * 32 + (lane >> 2);
    const int ncol0 = tn * 128 + wn * 64 + (lane & 3) * 2;
    #pragma unroll
    for (int mi = 0; mi < 2; mi++) {
        #pragma unroll
        for (int ni = 0; ni < 8; ni++) {
            const int r = mrow0 + mi * 16;
            const int cc = ncol0 + ni * 8;
            *(float2*)&Cn[(size_t)r * C + cc]       = make_float2(acc[mi][ni][0], acc[mi][ni][1]);
            *(float2*)&Cn[(size_t)(r + 8) * C + cc] = make_float2(acc[mi][ni][2], acc[mi][ni][3]);
        }
    }
}

// ---------------- kernel 3: fused split-K combine + row-softmax + partial column-sum ----------------
// grid (GRP, 16): CTA = 32 rows of batch n0+blockIdx.x.
__global__ void k_bsm(int n0) {
    __shared__ float cac[8][C];   // 16 KB
    const int n = n0 + blockIdx.x, cb = blockIdx.y;
    const int lane = threadIdx.x & 31, wid = threadIdx.x >> 5;

    float wacc[4][4];
    #pragma unroll
    for (int q = 0; q < 4; q++)
        #pragma unroll
        for (int j = 0; j < 4; j++) wacc[q][j] = 0.0f;

    for (int r = wid; r < 32; r += 8) {
        const int row = cb * 32 + r;
        const size_t ro = (size_t)n * C * C + (size_t)row * C;
        const float* B0 = g_Bp[0] + ro;
        const float* B1 = g_Bp[1] + ro;
        const float iz = g_invZ[n * C + row];
        float4 v[4];
        float m = -INFINITY;
        #pragma unroll
        for (int q = 0; q < 4; q++) {
            float4 u0 = *(const float4*)(B0 + q * 128 + lane * 4);
            float4 u1 = *(const float4*)(B1 + q * 128 + lane * 4);
            v[q].x = (u0.x + u1.x) * iz;
            v[q].y = (u0.y + u1.y) * iz;
            v[q].z = (u0.z + u1.z) * iz;
            v[q].w = (u0.w + u1.w) * iz;
            m = fmaxf(m, fmaxf(fmaxf(v[q].x, v[q].y), fmaxf(v[q].z, v[q].w)));
        }
        #pragma unroll
        for (int o = 16; o; o >>= 1) m = fmaxf(m, __shfl_xor_sync(0xffffffffu, m, o));
        float s = 0.0f;
        #pragma unroll
        for (int q = 0; q < 4; q++) {
            v[q].x = __expf(v[q].x - m); v[q].y = __expf(v[q].y - m);
            v[q].z = __expf(v[q].z - m); v[q].w = __expf(v[q].w - m);
            s += (v[q].x + v[q].y) + (v[q].z + v[q].w);
        }
        #pragma unroll
        for (int o = 16; o; o >>= 1) s += __shfl_xor_sync(0xffffffffu, s, o);
        const float inv = 1.0f / s;
        #pragma unroll
        for (int q = 0; q < 4; q++) {
            wacc[q][0] = fmaf(v[q].x, inv, wacc[q][0]);
            wacc[q][1] = fmaf(v[q].y, inv, wacc[q][1]);
            wacc[q][2] = fmaf(v[q].z, inv, wacc[q][2]);
            wacc[q][3] = fmaf(v[q].w, inv, wacc[q][3]);
        }
    }
    #pragma unroll
    for (int q = 0; q < 4; q++)
        *(float4*)&cac[wid][q * 128 + lane * 4] =
            make_float4(wacc[q][0], wacc[q][1], wacc[q][2], wacc[q][3]);
    __syncthreads();
    #pragma unroll
    for (int h = 0; h < 2; h++) {
        const int col = threadIdx.x + h * 256;
        float s = 0.0f;
        #pragma unroll
        for (int w = 0; w < 8; w++) s += cac[w][col];
        g_wpart[cb][n * C + col] = s;
    }
}

// ---------------- kernel 4: d-split partial output sums ----------------
#define S2 (S / 2)   // 1568 half2 per row
__global__ void k_out(int n0) {
    const int n = n0 + blockIdx.y;
    const int dq = blockIdx.z;                 // 0..7
    const int s2 = blockIdx.x * 256 + threadIdx.x;
    __shared__ float ws[64];
    if (threadIdx.x < 64) {
        const int d = dq * 64 + threadIdx.x;
        float s = 0.0f;
        #pragma unroll
        for (int w = 0; w < 16; w++) s += g_wpart[w][n * C + d];
        ws[threadIdx.x] = s;
    }
    __syncthreads();
    if (s2 >= S2) return;
    const __half2* fb = (const __half2*)(g_xh + (size_t)n * C * S + (size_t)(dq * 64) * S) + s2;
    float a0 = 0, a1 = 0, b0 = 0, b1 = 0;
    #pragma unroll 4
    for (int d = 0; d < 64; d += 2) {
        float2 f0 = __half22float2(fb[(size_t)d * S2]);
        float2 f1 = __half22float2(fb[(size_t)(d + 1) * S2]);
        a0 = fmaf(ws[d], f0.x, a0);
        a1 = fmaf(ws[d], f0.y, a1);
        b0 = fmaf(ws[d + 1], f1.x, b0);
        b1 = fmaf(ws[d + 1], f1.y, b1);
    }
    float2* o = (float2*)(g_opart[dq] + (size_t)n * S) + s2;
    *o = make_float2(a0 + b0, a1 + b1);
}

// ---------------- kernel 5: combine partials into out ----------------
__global__ void k_comb(float* __restrict__ out) {
    const int i4 = blockIdx.x * 256 + threadIdx.x;   // float4 index, NB*S/4 = 25088
    if (i4 >= NB * S / 4) return;
    float4 acc = make_float4(0.f, 0.f, 0.f, 0.f);
    #pragma unroll
    for (int q = 0; q < 8; q++) {
        float4 v = ((const float4*)g_opart[q])[i4];
        acc.x += v.x; acc.y += v.y; acc.z += v.z; acc.w += v.w;
    }
    ((float4*)out)[i4] = acc;
}

extern "C" void kernel_launch(void* const* d_in, const int* in_sizes, int n_in,
                              void* d_out, int out_size) {
    const float* x = (const float*)d_in[0];
    float* out = (float*)d_out;

    static bool init = false;
    static cudaStream_t s2;
    static cudaEvent_t evRoot, evR[NGRP], evG[NGRP];
    if (!init) {
        cudaFuncSetAttribute(k_gemm_mma, cudaFuncAttributeMaxDynamicSharedMemorySize, SMEM_TOTAL);
        cudaStreamCreateWithFlags(&s2, cudaStreamNonBlocking);
        cudaEventCreateWithFlags(&evRoot, cudaEventDisableTiming);
        for (int g = 0; g < NGRP; g++) {
            cudaEventCreateWithFlags(&evR[g], cudaEventDisableTiming);
            cudaEventCreateWithFlags(&evG[g], cudaEventDisableTiming);
        }
        init = true;
    }

    // fork s2 from the capturing (default) stream
    cudaEventRecord(evRoot, 0);
    cudaStreamWaitEvent(s2, evRoot, 0);

    // pipelined rowexp (stream 0) -> gemm (s2) per group of GRP batches
    for (int g = 0; g < NGRP; g++) {
        k_rowexp<<<GRP * C, 256>>>(x, g * GRP * C);
        cudaEventRecord(evR[g], 0);
        cudaStreamWaitEvent(s2, evR[g], 0);
        dim3 gg(C / 128, 8, GRP);   // (4, tm x kh, 8) = 256 CTA-works
        k_gemm_mma<<<gg, 256, SMEM_TOTAL, s2>>>(g * GRP);
        cudaEventRecord(evG[g], s2);
    }

    // per-group bsm + out on stream 0, overlapping later gemms
    for (int g = 0; g < NGRP; g++) {
        cudaStreamWaitEvent(0, evG[g], 0);
        dim3 g3(GRP, 16);
        k_bsm<<<g3, 256>>>(g * GRP);
        dim3 g4((S2 + 255) / 256, GRP, 8);
        k_out<<<g4, 256>>>(g * GRP);
    }

    k_comb<<<(NB * S / 4 + 255) / 256, 256>>>(out);
}